// round 2
// baseline (speedup 1.0000x reference)
#include <cuda_runtime.h>
#include <cuda_bf16.h>
#include <stdint.h>

// Problem constants
#define BATCH 8
#define LQ    1024
#define LKV   2048
#define HID   1024
#define QDIM  1024

// GEMM tiling
#define BM 128
#define BN 128
#define BK 16
#define TM 8
#define TN 8

// -------- scratch (static device globals; no runtime allocation) --------
__device__ float g_Q[(size_t)BATCH * LQ  * HID];   //  32 MB
__device__ float g_K[(size_t)BATCH * LKV * HID];   //  64 MB
__device__ float g_V[(size_t)BATCH * LKV * HID];   //  64 MB
__device__ float g_S[(size_t)BATCH * LQ  * LKV];   //  64 MB
__device__ float g_C[(size_t)BATCH * LQ  * HID];   //  32 MB
__device__ uint8_t g_mask[(size_t)BATCH * LKV];    //  16 KB canonical mask
__device__ int     g_mask_is_u8;                   //  layout flag

// ---------------------------------------------------------------
// Mask dtype detection. The harness may store the jax bool mask as
// int32 (one word per element) or uint8 (one byte per element).
// Scan the first 4096 int32 words (16 KB — safe under either layout:
// uint8 buffer is exactly 16384 bytes). If every word is 0 or 1, the
// layout is int32 (a packed-byte layout would show words like
// 0x00010001 with near-certainty over 4096 words). Single block.
// ---------------------------------------------------------------
__global__ void detect_mask_kernel(const void* __restrict__ mask_raw)
{
    __shared__ int bad;
    if (threadIdx.x == 0) bad = 0;
    __syncthreads();
    const int* w = (const int*)mask_raw;
    for (int i = threadIdx.x; i < 4096; i += blockDim.x) {
        unsigned v = (unsigned)w[i];
        if (v > 1u) atomicOr(&bad, 1);
    }
    __syncthreads();
    if (threadIdx.x == 0) g_mask_is_u8 = bad;   // bad words => byte layout
}

// Canonicalize mask into g_mask (uint8, one byte per key position).
__global__ void convert_mask_kernel(const void* __restrict__ mask_raw)
{
    const int n = BATCH * LKV;
    const int is_u8 = g_mask_is_u8;
    for (int i = blockIdx.x * blockDim.x + threadIdx.x; i < n;
         i += gridDim.x * blockDim.x) {
        uint8_t m;
        if (is_u8) m = ((const uint8_t*)mask_raw)[i] ? 1 : 0;
        else       m = ((const int*)mask_raw)[i]     ? 1 : 0;
        g_mask[i] = m;
    }
}

// ---------------------------------------------------------------
// Generic tiled GEMM:
//   C[M,N] = A[M,K] @ op(B) (+ epilogue)
//   TRANSB=false: B is [K,N] row-major
//   TRANSB=true : B is [N,K] row-major (computes A @ B^T)
//   EPI: 0 = +bias[N], 1 = *scale then mask (else -1e9), 2 = plain
// Batched via blockIdx.z with element strides. All dims assumed
// multiples of BM/BN/BK (true for this problem).
// ---------------------------------------------------------------
template <bool TRANSB, int EPI>
__global__ void __launch_bounds__(256, 2)
gemm_kernel(const float* __restrict__ A,
            const float* __restrict__ B,
            float*       __restrict__ C,
            const float* __restrict__ bias,
            const uint8_t* __restrict__ mask,
            float scale,
            int M, int N, int K,
            long long strideA, long long strideB, long long strideC,
            long long strideMask)
{
    __shared__ float As[BK][BM];
    __shared__ float Bs[BK][BN];

    const int b = blockIdx.z;
    A += (long long)b * strideA;
    B += (long long)b * strideB;
    C += (long long)b * strideC;

    const int tileM = blockIdx.y * BM;
    const int tileN = blockIdx.x * BN;
    const int tid   = threadIdx.x;  // 256 threads

    float acc[TM][TN];
    #pragma unroll
    for (int i = 0; i < TM; i++)
        #pragma unroll
        for (int j = 0; j < TN; j++) acc[i][j] = 0.0f;

    const int rowB = (tid >> 4) * TM;   // 0..120
    const int colB = (tid & 15) * TN;   // 0..120

    for (int k0 = 0; k0 < K; k0 += BK) {
        // ---- load A tile [BM x BK], store transposed As[k][m] ----
        #pragma unroll
        for (int i = 0; i < 2; i++) {
            int f  = tid + i * 256;          // 0..511
            int r  = f >> 2;                 // row 0..127
            int c4 = (f & 3) << 2;           // k offset 0,4,8,12
            float4 v = *(const float4*)(A + (long long)(tileM + r) * K + k0 + c4);
            As[c4 + 0][r] = v.x;
            As[c4 + 1][r] = v.y;
            As[c4 + 2][r] = v.z;
            As[c4 + 3][r] = v.w;
        }
        // ---- load B tile into Bs[k][n] ----
        if (!TRANSB) {
            #pragma unroll
            for (int i = 0; i < 2; i++) {
                int f  = tid + i * 256;
                int kk = f >> 5;             // 0..15
                int c  = (f & 31) << 2;      // n offset 0..124
                float4 v = *(const float4*)(B + (long long)(k0 + kk) * N + tileN + c);
                *(float4*)&Bs[kk][c] = v;
            }
        } else {
            #pragma unroll
            for (int i = 0; i < 2; i++) {
                int f  = tid + i * 256;
                int n  = f >> 2;             // 0..127
                int k4 = (f & 3) << 2;       // 0,4,8,12
                float4 v = *(const float4*)(B + (long long)(tileN + n) * K + k0 + k4);
                Bs[k4 + 0][n] = v.x;
                Bs[k4 + 1][n] = v.y;
                Bs[k4 + 2][n] = v.z;
                Bs[k4 + 3][n] = v.w;
            }
        }
        __syncthreads();

        // ---- compute ----
        #pragma unroll
        for (int kk = 0; kk < BK; kk++) {
            float a[TM], bb[TN];
            #pragma unroll
            for (int i = 0; i < TM; i++) a[i]  = As[kk][rowB + i];
            #pragma unroll
            for (int j = 0; j < TN; j++) bb[j] = Bs[kk][colB + j];
            #pragma unroll
            for (int i = 0; i < TM; i++)
                #pragma unroll
                for (int j = 0; j < TN; j++)
                    acc[i][j] = fmaf(a[i], bb[j], acc[i][j]);
        }
        __syncthreads();
    }

    // ---- epilogue ----
    const int row0 = tileM + rowB;
    const int col0 = tileN + colB;

    if (EPI == 0) {
        float bv[TN];
        #pragma unroll
        for (int j = 0; j < TN; j++) bv[j] = bias[col0 + j];
        #pragma unroll
        for (int i = 0; i < TM; i++) {
            float4 o0 = make_float4(acc[i][0] + bv[0], acc[i][1] + bv[1],
                                    acc[i][2] + bv[2], acc[i][3] + bv[3]);
            float4 o1 = make_float4(acc[i][4] + bv[4], acc[i][5] + bv[5],
                                    acc[i][6] + bv[6], acc[i][7] + bv[7]);
            float* cp = C + (long long)(row0 + i) * N + col0;
            *(float4*)(cp)     = o0;
            *(float4*)(cp + 4) = o1;
        }
    } else if (EPI == 1) {
        const uint8_t* m = mask + (long long)b * strideMask;
        float mv[TN];
        #pragma unroll
        for (int j = 0; j < TN; j++) mv[j] = m[col0 + j] ? 1.0f : 0.0f;
        #pragma unroll
        for (int i = 0; i < TM; i++) {
            float o[TN];
            #pragma unroll
            for (int j = 0; j < TN; j++)
                o[j] = mv[j] != 0.0f ? acc[i][j] * scale : -1e9f;
            float* cp = C + (long long)(row0 + i) * N + col0;
            *(float4*)(cp)     = make_float4(o[0], o[1], o[2], o[3]);
            *(float4*)(cp + 4) = make_float4(o[4], o[5], o[6], o[7]);
        }
    } else {
        #pragma unroll
        for (int i = 0; i < TM; i++) {
            float* cp = C + (long long)(row0 + i) * N + col0;
            *(float4*)(cp)     = make_float4(acc[i][0], acc[i][1], acc[i][2], acc[i][3]);
            *(float4*)(cp + 4) = make_float4(acc[i][4], acc[i][5], acc[i][6], acc[i][7]);
        }
    }
}

// ---------------------------------------------------------------
// Row softmax over S[B*LQ, LKV]. One block (256 threads) per row.
// ---------------------------------------------------------------
__global__ void __launch_bounds__(256)
softmax_kernel(float* __restrict__ S)
{
    float* row = S + (long long)blockIdx.x * LKV;
    const int tid = threadIdx.x;
    const int PER = LKV / 256;  // 8

    float vals[PER];
    float mx = -1e30f;
    #pragma unroll
    for (int i = 0; i < PER; i++) {
        vals[i] = row[tid + i * 256];
        mx = fmaxf(mx, vals[i]);
    }

    __shared__ float red[8];
    // warp-reduce max
    #pragma unroll
    for (int o = 16; o > 0; o >>= 1)
        mx = fmaxf(mx, __shfl_xor_sync(0xFFFFFFFFu, mx, o));
    if ((tid & 31) == 0) red[tid >> 5] = mx;
    __syncthreads();
    if (tid == 0) {
        float v = red[0];
        #pragma unroll
        for (int w = 1; w < 8; w++) v = fmaxf(v, red[w]);
        red[0] = v;
    }
    __syncthreads();
    mx = red[0];

    float sum = 0.0f;
    #pragma unroll
    for (int i = 0; i < PER; i++) {
        vals[i] = __expf(vals[i] - mx);
        sum += vals[i];
    }
    __syncthreads();
    #pragma unroll
    for (int o = 16; o > 0; o >>= 1)
        sum += __shfl_xor_sync(0xFFFFFFFFu, sum, o);
    if ((tid & 31) == 0) red[tid >> 5] = sum;
    __syncthreads();
    if (tid == 0) {
        float v = red[0];
        #pragma unroll
        for (int w = 1; w < 8; w++) v += red[w];
        red[0] = v;
    }
    __syncthreads();
    const float inv = 1.0f / red[0];

    #pragma unroll
    for (int i = 0; i < PER; i++)
        row[tid + i * 256] = vals[i] * inv;
}

// ---------------------------------------------------------------
// Host launcher
// ---------------------------------------------------------------
extern "C" void kernel_launch(void* const* d_in, const int* in_sizes, int n_in,
                              void* d_out, int out_size)
{
    const float* query = (const float*)d_in[0];  // [B, LQ, QDIM]
    const float* kv    = (const float*)d_in[1];  // [B, LKV, KDIM]
    const void*  mask  = d_in[2];                // [B, LKV] bool (dtype detected on-device)
    const float* Wq = (const float*)d_in[3];
    const float* bq = (const float*)d_in[4];
    const float* Wk = (const float*)d_in[5];
    const float* bk = (const float*)d_in[6];
    const float* Wv = (const float*)d_in[7];
    const float* bv = (const float*)d_in[8];
    const float* Wo = (const float*)d_in[9];
    const float* bo = (const float*)d_in[10];
    float* out = (float*)d_out;  // [B, LQ, QDIM]

    float *Q, *K, *V, *S, *C;
    uint8_t* M;
    cudaGetSymbolAddress((void**)&Q, g_Q);
    cudaGetSymbolAddress((void**)&K, g_K);
    cudaGetSymbolAddress((void**)&V, g_V);
    cudaGetSymbolAddress((void**)&S, g_S);
    cudaGetSymbolAddress((void**)&C, g_C);
    cudaGetSymbolAddress((void**)&M, g_mask);

    const float scale = 1.0f / 32.0f;  // 1/sqrt(1024)

    // 0. mask dtype detection + canonicalization
    detect_mask_kernel<<<1, 256>>>(mask);
    convert_mask_kernel<<<32, 256>>>(mask);

    // 1. Q projection: [B*LQ, QDIM] @ [QDIM, HID] + bq
    gemm_kernel<false, 0><<<dim3(HID / BN, (BATCH * LQ) / BM, 1), 256>>>(
        query, Wq, Q, bq, nullptr, 0.0f,
        BATCH * LQ, HID, QDIM, 0, 0, 0, 0);

    // 2. K projection: [B*LKV, KDIM] @ [KDIM, HID] + bk
    gemm_kernel<false, 0><<<dim3(HID / BN, (BATCH * LKV) / BM, 1), 256>>>(
        kv, Wk, K, bk, nullptr, 0.0f,
        BATCH * LKV, HID, 1024, 0, 0, 0, 0);

    // 3. V projection
    gemm_kernel<false, 0><<<dim3(HID / BN, (BATCH * LKV) / BM, 1), 256>>>(
        kv, Wv, V, bv, nullptr, 0.0f,
        BATCH * LKV, HID, 1024, 0, 0, 0, 0);

    // 4. scores: per batch, S[LQ, LKV] = (Q @ K^T) * scale, masked
    gemm_kernel<true, 1><<<dim3(LKV / BN, LQ / BM, BATCH), 256>>>(
        Q, K, S, nullptr, M, scale,
        LQ, LKV, HID,
        (long long)LQ * HID, (long long)LKV * HID, (long long)LQ * LKV,
        (long long)LKV);

    // 5. row softmax over S
    softmax_kernel<<<BATCH * LQ, 256>>>(S);

    // 6. context: per batch, C[LQ, HID] = P[LQ, LKV] @ V[LKV, HID]
    gemm_kernel<false, 2><<<dim3(HID / BN, LQ / BM, BATCH), 256>>>(
        S, V, C, nullptr, nullptr, 0.0f,
        LQ, HID, LKV,
        (long long)LQ * LKV, (long long)LKV * HID, (long long)LQ * HID, 0);

    // 7. output projection: out = C @ Wo + bo
    gemm_kernel<false, 0><<<dim3(QDIM / BN, (BATCH * LQ) / BM, 1), 256>>>(
        C, Wo, out, bo, nullptr, 0.0f,
        BATCH * LQ, QDIM, HID, 0, 0, 0, 0);
}

// round 4
// speedup vs baseline: 2.5647x; 2.5647x over previous
#include <cuda_runtime.h>
#include <cuda_bf16.h>
#include <stdint.h>

// Problem constants
#define BATCH 8
#define LQ    1024
#define LKV   2048
#define HID   1024
#define QDIM  1024

typedef __nv_bfloat16 bf16;

// ================= scratch (static device globals) =================
// split inputs
__device__ __align__(16) bf16 g_qh [(size_t)BATCH * LQ  * QDIM];
__device__ __align__(16) bf16 g_ql [(size_t)BATCH * LQ  * QDIM];
__device__ __align__(16) bf16 g_kvh[(size_t)BATCH * LKV * QDIM];
__device__ __align__(16) bf16 g_kvl[(size_t)BATCH * LKV * QDIM];
// transposed split weights [N][K]
__device__ __align__(16) bf16 g_WqTh[(size_t)HID * QDIM];
__device__ __align__(16) bf16 g_WqTl[(size_t)HID * QDIM];
__device__ __align__(16) bf16 g_WkTh[(size_t)HID * QDIM];
__device__ __align__(16) bf16 g_WkTl[(size_t)HID * QDIM];
__device__ __align__(16) bf16 g_WvTh[(size_t)HID * QDIM];
__device__ __align__(16) bf16 g_WvTl[(size_t)HID * QDIM];
__device__ __align__(16) bf16 g_WoTh[(size_t)HID * QDIM];
__device__ __align__(16) bf16 g_WoTl[(size_t)HID * QDIM];
// intermediates
__device__ __align__(16) bf16  g_Qh [(size_t)BATCH * LQ  * HID];
__device__ __align__(16) bf16  g_Ql [(size_t)BATCH * LQ  * HID];
__device__ __align__(16) bf16  g_Kh [(size_t)BATCH * LKV * HID];
__device__ __align__(16) bf16  g_Kl [(size_t)BATCH * LKV * HID];
__device__ __align__(16) float g_Vf [(size_t)BATCH * LKV * HID];
__device__ __align__(16) bf16  g_VTh[(size_t)BATCH * HID * LKV];
__device__ __align__(16) bf16  g_VTl[(size_t)BATCH * HID * LKV];
__device__ __align__(16) float g_Sf [(size_t)BATCH * LQ  * LKV];
__device__ __align__(16) bf16  g_Ph [(size_t)BATCH * LQ  * LKV];
__device__ __align__(16) bf16  g_Pl [(size_t)BATCH * LQ  * LKV];
__device__ __align__(16) bf16  g_Ch [(size_t)BATCH * LQ  * HID];
__device__ __align__(16) bf16  g_Cl [(size_t)BATCH * LQ  * HID];
__device__ uint8_t g_mask[(size_t)BATCH * LKV];
__device__ int     g_mask_is_u8;

// ================= PTX helpers (sm_100 base target only) =================
__device__ __forceinline__ uint32_t smem_to_u32(const void* p) {
    uint32_t a;
    asm("{ .reg .u64 t; cvta.to.shared.u64 t, %1; cvt.u32.u64 %0, t; }"
        : "=r"(a) : "l"(p));
    return a;
}

#define SWZ128(o) ((o) ^ (((o) >> 3) & 0x70))

__device__ __forceinline__ void cp16(uint32_t saddr, const void* g) {
    asm volatile("cp.async.cg.shared.global [%0], [%1], 16;"
                 :: "r"(saddr), "l"(g) : "memory");
}
#define CP_COMMIT() asm volatile("cp.async.commit_group;" ::: "memory")
#define CP_WAIT1()  asm volatile("cp.async.wait_group 1;" ::: "memory")
#define CP_WAIT0()  asm volatile("cp.async.wait_group 0;" ::: "memory")

__device__ __forceinline__ void ldsm4(uint32_t* r, uint32_t addr) {
    asm volatile("ldmatrix.sync.aligned.m8n8.x4.shared.b16 {%0,%1,%2,%3}, [%4];"
                 : "=r"(r[0]), "=r"(r[1]), "=r"(r[2]), "=r"(r[3]) : "r"(addr));
}

__device__ __forceinline__ void mma16816(float* d, const uint32_t* a,
                                         uint32_t b0, uint32_t b1) {
    asm volatile(
        "mma.sync.aligned.m16n8k16.row.col.f32.bf16.bf16.f32 "
        "{%0,%1,%2,%3}, {%4,%5,%6,%7}, {%8,%9}, {%0,%1,%2,%3};"
        : "+f"(d[0]), "+f"(d[1]), "+f"(d[2]), "+f"(d[3])
        : "r"(a[0]), "r"(a[1]), "r"(a[2]), "r"(a[3]), "r"(b0), "r"(b1));
}

__device__ __forceinline__ void split1(float v, bf16& h, bf16& l) {
    h = __float2bfloat16(v);
    l = __float2bfloat16(v - __bfloat162float(h));
}

// ================= mask detection / canonicalization =================
__global__ void detect_mask_kernel(const void* __restrict__ mask_raw) {
    __shared__ int bad;
    if (threadIdx.x == 0) bad = 0;
    __syncthreads();
    const int* w = (const int*)mask_raw;
    for (int i = threadIdx.x; i < 4096; i += blockDim.x)
        if ((unsigned)w[i] > 1u) atomicOr(&bad, 1);
    __syncthreads();
    if (threadIdx.x == 0) g_mask_is_u8 = bad;
}

__global__ void convert_mask_kernel(const void* __restrict__ mask_raw) {
    const int n = BATCH * LKV;
    const int is_u8 = g_mask_is_u8;
    for (int i = blockIdx.x * blockDim.x + threadIdx.x; i < n;
         i += gridDim.x * blockDim.x) {
        uint8_t m;
        if (is_u8) m = ((const uint8_t*)mask_raw)[i] ? 1 : 0;
        else       m = ((const int*)mask_raw)[i]     ? 1 : 0;
        g_mask[i] = m;
    }
}

// ================= elementwise fp32 -> bf16 hi/lo split =================
__global__ void __launch_bounds__(256)
split_kernel(const float* __restrict__ x, bf16* __restrict__ h,
             bf16* __restrict__ l, long long n4)
{
    long long i = blockIdx.x * 256 + threadIdx.x;
    if (i >= n4) return;
    float4 v = *(const float4*)(x + i * 4);
    bf16 hh[4], ll[4];
    split1(v.x, hh[0], ll[0]);
    split1(v.y, hh[1], ll[1]);
    split1(v.z, hh[2], ll[2]);
    split1(v.w, hh[3], ll[3]);
    *(uint2*)(h + i * 4) = *(uint2*)hh;
    *(uint2*)(l + i * 4) = *(uint2*)ll;
}

// ============== tiled transpose + split: x[R][C] -> out[C][R] ==============
__global__ void __launch_bounds__(256)
tsplit_kernel(const float* __restrict__ x, bf16* __restrict__ th,
              bf16* __restrict__ tl, int R, int C,
              long long sIn, long long sOut)
{
    __shared__ float t[32][33];
    x  += (long long)blockIdx.z * sIn;
    th += (long long)blockIdx.z * sOut;
    tl += (long long)blockIdx.z * sOut;
    const int bc = blockIdx.x * 32;   // C offset
    const int br = blockIdx.y * 32;   // R offset
    const int tx = threadIdx.x, ty = threadIdx.y;
    #pragma unroll
    for (int j = 0; j < 32; j += 8)
        t[ty + j][tx] = x[(long long)(br + ty + j) * C + bc + tx];
    __syncthreads();
    #pragma unroll
    for (int j = 0; j < 32; j += 8) {
        float v = t[tx][ty + j];
        bf16 h, l;
        split1(v, h, l);
        long long o = (long long)(bc + ty + j) * R + br + tx;
        th[o] = h;
        tl[o] = l;
    }
}

// ================= bf16x3 HMMA GEMM =================
// C[M,N] = A[M,K] @ B[N,K]^T with A = Ah+Al, B = Bh+Bl (bf16 hi/lo).
// 3 mma passes: Ah*Bh + Ah*Bl + Al*Bh, fp32 accumulate.
// CTA tile 128x128, K-tile 64, 8 warps (4M x 2N, each 32x64).
// EPI: 0 = +bias -> split hi/lo out
//      1 = +bias -> fp32 out
//      2 = *scale, mask else -1e9 -> fp32 out
//      3 = plain -> split hi/lo out
#define BKT 64
#define STAGE_B 65536   // 4 subtiles x 16KB (Ah, Al, Bh, Bl)
#define DSMEM_B (2 * STAGE_B)

template <int EPI>
__global__ void __launch_bounds__(256, 1)
mma_gemm(const bf16* __restrict__ Ah, const bf16* __restrict__ Al,
         const bf16* __restrict__ Bh, const bf16* __restrict__ Bl,
         float* __restrict__ Cf, bf16* __restrict__ Oh, bf16* __restrict__ Ol,
         const float* __restrict__ bias, const uint8_t* __restrict__ mask,
         float scale, int N, int Kd,
         long long sA, long long sB, long long sC, long long sMask)
{
    extern __shared__ char smem[];
    const uint32_t sbase = smem_to_u32(smem);

    const int tid  = threadIdx.x;
    const int b    = blockIdx.z;
    const int tileM = blockIdx.y * 128;
    const int tileN = blockIdx.x * 128;

    const bf16* baseA[2] = {Ah + (long long)b * sA + (long long)tileM * Kd,
                            Al + (long long)b * sA + (long long)tileM * Kd};
    const bf16* baseB[2] = {Bh + (long long)b * sB + (long long)tileN * Kd,
                            Bl + (long long)b * sB + (long long)tileN * Kd};

    const int wid = tid >> 5, lane = tid & 31;
    const int wm = wid & 3;        // 0..3 -> 32-row strip
    const int wn = wid >> 2;       // 0..1 -> 64-col strip

    float acc[2][8][4];
    #pragma unroll
    for (int mi = 0; mi < 2; mi++)
        #pragma unroll
        for (int nj = 0; nj < 8; nj++)
            #pragma unroll
            for (int q = 0; q < 4; q++) acc[mi][nj][q] = 0.0f;

    const int KT = Kd / BKT;

    // precompute per-thread load coords: chunk c = i*256+tid, r=c>>3, kc=c&7
    // ---- stage loader ----
    auto load_stage = [&](int kt, int s) {
        const int k0 = kt * BKT;
        #pragma unroll
        for (int sub = 0; sub < 4; sub++) {
            const bf16* gb = (sub < 2) ? baseA[sub] : baseB[sub - 2];
            const uint32_t so = sbase + s * STAGE_B + sub * 16384;
            #pragma unroll
            for (int i = 0; i < 4; i++) {
                const int c  = i * 256 + tid;
                const int r  = c >> 3;
                const int kc = c & 7;
                cp16(so + SWZ128((uint32_t)(r * 128 + kc * 16)),
                     gb + (long long)r * Kd + k0 + kc * 8);
            }
        }
        CP_COMMIT();
    };

    load_stage(0, 0);

    for (int kt = 0; kt < KT; kt++) {
        const int s = kt & 1;
        if (kt + 1 < KT) {
            load_stage(kt + 1, (kt + 1) & 1);
            CP_WAIT1();
        } else {
            CP_WAIT0();
        }
        __syncthreads();

        const uint32_t aH = sbase + s * STAGE_B;
        const uint32_t aL = aH + 16384;
        const uint32_t bH = aH + 32768;
        const uint32_t bL = aH + 49152;

        #pragma unroll
        for (int ks = 0; ks < 4; ks++) {
            const int chunk = ks * 32 + (lane >> 4) * 16;
            uint32_t ah[2][4], al[2][4];
            #pragma unroll
            for (int mi = 0; mi < 2; mi++) {
                const int r = wm * 32 + mi * 16 + (lane & 15);
                const uint32_t off = SWZ128((uint32_t)(r * 128 + chunk));
                ldsm4(ah[mi], aH + off);
                ldsm4(al[mi], aL + off);
            }
            uint32_t bh[4][4], bl[4][4];
            #pragma unroll
            for (int ni = 0; ni < 4; ni++) {
                const int r = wn * 64 + ni * 16 + (lane & 15);
                const uint32_t off = SWZ128((uint32_t)(r * 128 + chunk));
                ldsm4(bh[ni], bH + off);
                ldsm4(bl[ni], bL + off);
            }
            #pragma unroll
            for (int mi = 0; mi < 2; mi++) {
                #pragma unroll
                for (int nj = 0; nj < 8; nj++) {
                    const int ni = nj >> 1, oct = nj & 1;
                    mma16816(acc[mi][nj], ah[mi], bh[ni][oct], bh[ni][oct + 2]);
                    mma16816(acc[mi][nj], ah[mi], bl[ni][oct], bl[ni][oct + 2]);
                    mma16816(acc[mi][nj], al[mi], bh[ni][oct], bh[ni][oct + 2]);
                }
            }
        }
        __syncthreads();
    }

    // ---- epilogue ----
    float* cf = Cf ? Cf + (long long)b * sC : nullptr;
    bf16*  oh = Oh ? Oh + (long long)b * sC : nullptr;
    bf16*  ol = Ol ? Ol + (long long)b * sC : nullptr;
    const uint8_t* mk = mask ? mask + (long long)b * sMask : nullptr;

    #pragma unroll
    for (int mi = 0; mi < 2; mi++) {
        #pragma unroll
        for (int nj = 0; nj < 8; nj++) {
            const int row = tileM + wm * 32 + mi * 16 + (lane >> 2);
            const int col = tileN + wn * 64 + nj * 8 + (lane & 3) * 2;
            #pragma unroll
            for (int half = 0; half < 2; half++) {
                const int r = row + half * 8;
                float v0 = acc[mi][nj][half * 2];
                float v1 = acc[mi][nj][half * 2 + 1];
                if (EPI == 0 || EPI == 1) {
                    v0 += __ldg(bias + col);
                    v1 += __ldg(bias + col + 1);
                } else if (EPI == 2) {
                    v0 = mk[col]     ? v0 * scale : -1e9f;
                    v1 = mk[col + 1] ? v1 * scale : -1e9f;
                }
                if (EPI == 1 || EPI == 2) {
                    *(float2*)(cf + (long long)r * N + col) = make_float2(v0, v1);
                } else {
                    bf16 h2[2], l2[2];
                    split1(v0, h2[0], l2[0]);
                    split1(v1, h2[1], l2[1]);
                    *(uint32_t*)(oh + (long long)r * N + col) = *(uint32_t*)h2;
                    *(uint32_t*)(ol + (long long)r * N + col) = *(uint32_t*)l2;
                }
            }
        }
    }
}

// ============ softmax: S fp32 row -> P hi/lo bf16 ============
__global__ void __launch_bounds__(256)
softmax_kernel(const float* __restrict__ S, bf16* __restrict__ Ph,
               bf16* __restrict__ Pl)
{
    const long long ro = (long long)blockIdx.x * LKV;
    const float* row = S + ro;
    const int tid = threadIdx.x;
    const int PER = LKV / 256;  // 8

    float vals[PER];
    float mx = -1e30f;
    #pragma unroll
    for (int i = 0; i < PER; i++) {
        vals[i] = row[tid + i * 256];
        mx = fmaxf(mx, vals[i]);
    }

    __shared__ float red[8];
    #pragma unroll
    for (int o = 16; o > 0; o >>= 1)
        mx = fmaxf(mx, __shfl_xor_sync(0xFFFFFFFFu, mx, o));
    if ((tid & 31) == 0) red[tid >> 5] = mx;
    __syncthreads();
    if (tid == 0) {
        float v = red[0];
        #pragma unroll
        for (int w = 1; w < 8; w++) v = fmaxf(v, red[w]);
        red[0] = v;
    }
    __syncthreads();
    mx = red[0];

    float sum = 0.0f;
    #pragma unroll
    for (int i = 0; i < PER; i++) {
        vals[i] = __expf(vals[i] - mx);
        sum += vals[i];
    }
    __syncthreads();
    #pragma unroll
    for (int o = 16; o > 0; o >>= 1)
        sum += __shfl_xor_sync(0xFFFFFFFFu, sum, o);
    if ((tid & 31) == 0) red[tid >> 5] = sum;
    __syncthreads();
    if (tid == 0) {
        float v = red[0];
        #pragma unroll
        for (int w = 1; w < 8; w++) v += red[w];
        red[0] = v;
    }
    __syncthreads();
    const float inv = 1.0f / red[0];

    #pragma unroll
    for (int i = 0; i < PER; i++) {
        bf16 h, l;
        split1(vals[i] * inv, h, l);
        Ph[ro + tid + i * 256] = h;
        Pl[ro + tid + i * 256] = l;
    }
}

// ================= host launcher =================
extern "C" void kernel_launch(void* const* d_in, const int* in_sizes, int n_in,
                              void* d_out, int out_size)
{
    const float* query = (const float*)d_in[0];
    const float* kv    = (const float*)d_in[1];
    const void*  mask  = d_in[2];
    const float* Wq = (const float*)d_in[3];
    const float* bq = (const float*)d_in[4];
    const float* Wk = (const float*)d_in[5];
    const float* bk = (const float*)d_in[6];
    const float* Wv = (const float*)d_in[7];
    const float* bv = (const float*)d_in[8];
    const float* Wo = (const float*)d_in[9];
    const float* bo = (const float*)d_in[10];
    float* out = (float*)d_out;

    // resolve device symbols
    bf16 *qh, *ql, *kvh, *kvl;
    bf16 *WqTh, *WqTl, *WkTh, *WkTl, *WvTh, *WvTl, *WoTh, *WoTl;
    bf16 *Qh, *Ql, *Kh, *Kl, *VTh, *VTl, *Ph, *Pl, *Ch, *Cl;
    float *Vf, *Sf;
    uint8_t* M;
    cudaGetSymbolAddress((void**)&qh,  g_qh);   cudaGetSymbolAddress((void**)&ql,  g_ql);
    cudaGetSymbolAddress((void**)&kvh, g_kvh);  cudaGetSymbolAddress((void**)&kvl, g_kvl);
    cudaGetSymbolAddress((void**)&WqTh, g_WqTh); cudaGetSymbolAddress((void**)&WqTl, g_WqTl);
    cudaGetSymbolAddress((void**)&WkTh, g_WkTh); cudaGetSymbolAddress((void**)&WkTl, g_WkTl);
    cudaGetSymbolAddress((void**)&WvTh, g_WvTh); cudaGetSymbolAddress((void**)&WvTl, g_WvTl);
    cudaGetSymbolAddress((void**)&WoTh, g_WoTh); cudaGetSymbolAddress((void**)&WoTl, g_WoTl);
    cudaGetSymbolAddress((void**)&Qh, g_Qh);    cudaGetSymbolAddress((void**)&Ql, g_Ql);
    cudaGetSymbolAddress((void**)&Kh, g_Kh);    cudaGetSymbolAddress((void**)&Kl, g_Kl);
    cudaGetSymbolAddress((void**)&Vf, g_Vf);
    cudaGetSymbolAddress((void**)&VTh, g_VTh);  cudaGetSymbolAddress((void**)&VTl, g_VTl);
    cudaGetSymbolAddress((void**)&Sf, g_Sf);
    cudaGetSymbolAddress((void**)&Ph, g_Ph);    cudaGetSymbolAddress((void**)&Pl, g_Pl);
    cudaGetSymbolAddress((void**)&Ch, g_Ch);    cudaGetSymbolAddress((void**)&Cl, g_Cl);
    cudaGetSymbolAddress((void**)&M,  g_mask);

    cudaFuncSetAttribute(mma_gemm<0>, cudaFuncAttributeMaxDynamicSharedMemorySize, DSMEM_B);
    cudaFuncSetAttribute(mma_gemm<1>, cudaFuncAttributeMaxDynamicSharedMemorySize, DSMEM_B);
    cudaFuncSetAttribute(mma_gemm<2>, cudaFuncAttributeMaxDynamicSharedMemorySize, DSMEM_B);
    cudaFuncSetAttribute(mma_gemm<3>, cudaFuncAttributeMaxDynamicSharedMemorySize, DSMEM_B);

    const float scale = 1.0f / 32.0f;  // 1/sqrt(1024)

    // 0. mask + input preprocessing
    detect_mask_kernel<<<1, 256>>>(mask);
    convert_mask_kernel<<<32, 256>>>(mask);
    split_kernel<<<(int)(((long long)BATCH * LQ * QDIM / 4 + 255) / 256), 256>>>(
        query, qh, ql, (long long)BATCH * LQ * QDIM / 4);
    split_kernel<<<(int)(((long long)BATCH * LKV * QDIM / 4 + 255) / 256), 256>>>(
        kv, kvh, kvl, (long long)BATCH * LKV * QDIM / 4);
    {
        dim3 tb(32, 8), tg(HID / 32, QDIM / 32, 1);
        tsplit_kernel<<<tg, tb>>>(Wq, WqTh, WqTl, QDIM, HID, 0, 0);
        tsplit_kernel<<<tg, tb>>>(Wk, WkTh, WkTl, QDIM, HID, 0, 0);
        tsplit_kernel<<<tg, tb>>>(Wv, WvTh, WvTl, QDIM, HID, 0, 0);
        tsplit_kernel<<<tg, tb>>>(Wo, WoTh, WoTl, HID, QDIM, 0, 0);
    }

    // 1. Q projection -> Qh/Ql   [8192,1024] @ WqT[1024,1024]^T
    mma_gemm<0><<<dim3(HID / 128, (BATCH * LQ) / 128, 1), 256, DSMEM_B>>>(
        qh, ql, WqTh, WqTl, nullptr, Qh, Ql, bq, nullptr, 0.0f,
        HID, QDIM, 0, 0, 0, 0);

    // 2. K projection -> Kh/Kl   [16384,1024]
    mma_gemm<0><<<dim3(HID / 128, (BATCH * LKV) / 128, 1), 256, DSMEM_B>>>(
        kvh, kvl, WkTh, WkTl, nullptr, Kh, Kl, bk, nullptr, 0.0f,
        HID, QDIM, 0, 0, 0, 0);

    // 3. V projection -> Vf fp32
    mma_gemm<1><<<dim3(HID / 128, (BATCH * LKV) / 128, 1), 256, DSMEM_B>>>(
        kvh, kvl, WvTh, WvTl, Vf, nullptr, nullptr, bv, nullptr, 0.0f,
        HID, QDIM, 0, 0, 0, 0);

    // 3b. per-batch transpose V[LKV,HID] -> VT[HID,LKV] hi/lo
    {
        dim3 tb(32, 8), tg(HID / 32, LKV / 32, BATCH);
        tsplit_kernel<<<tg, tb>>>(Vf, VTh, VTl, LKV, HID,
                                  (long long)LKV * HID, (long long)HID * LKV);
    }

    // 4. scores: per batch S = mask(Q @ K^T * scale)  -> Sf fp32
    mma_gemm<2><<<dim3(LKV / 128, LQ / 128, BATCH), 256, DSMEM_B>>>(
        Qh, Ql, Kh, Kl, Sf, nullptr, nullptr, nullptr, M, scale,
        LKV, HID,
        (long long)LQ * HID, (long long)LKV * HID, (long long)LQ * LKV,
        (long long)LKV);

    // 5. softmax -> Ph/Pl
    softmax_kernel<<<BATCH * LQ, 256>>>(Sf, Ph, Pl);

    // 6. context: per batch C = P[LQ,LKV] @ VT[HID,LKV]^T -> Ch/Cl
    mma_gemm<3><<<dim3(HID / 128, LQ / 128, BATCH), 256, DSMEM_B>>>(
        Ph, Pl, VTh, VTl, nullptr, Ch, Cl, nullptr, nullptr, 0.0f,
        HID, LKV,
        (long long)LQ * LKV, (long long)HID * LKV, (long long)LQ * HID, 0);

    // 7. output projection: out = C @ WoT^T + bo  (fp32)
    mma_gemm<1><<<dim3(QDIM / 128, (BATCH * LQ) / 128, 1), 256, DSMEM_B>>>(
        Ch, Cl, WoTh, WoTl, out, nullptr, nullptr, bo, nullptr, 0.0f,
        QDIM, HID, 0, 0, 0, 0);
}